// round 7
// baseline (speedup 1.0000x reference)
#include <cuda_runtime.h>
#include <math.h>
#include <stdint.h>

#define G    64
#define NN   1024
#define KTOP 128
#define CH   8                               // graphs per chunk
#define NE   (G * NN * 32)                   // 2,097,152 edges
#define MATS ((size_t)NN * NN)               // 1,048,576
#define CTOT ((size_t)CH * MATS)             // 8,388,608 floats per buffer
#define OUTM ((size_t)G * NN * KTOP)         // 8,388,608

// 3 x 32MB rotating scratch buffers
__device__ __align__(16) float g_scratch[3 * CTOT];
__device__ __align__(16) float g_dis[CH * NN];

__device__ __forceinline__ float* BUF(int i) { return g_scratch + (size_t)i * CTOT; }

// ---------------------------------------------------------------------------
// initialize full output with a valid default (col half correct, row=col),
// written as FLOAT32 — the harness output dtype.
// ---------------------------------------------------------------------------
__global__ void out_init_kernel(float* __restrict__ out)
{
    size_t i  = (size_t)blockIdx.x * blockDim.x + threadIdx.x;
    size_t st = (size_t)gridDim.x * blockDim.x;
    for (; i < OUTM; i += st) {
        int g = (int)(i / (NN * KTOP));
        int j = (int)((i / KTOP) & 1023);
        float v = (float)((g << 10) + j);
        out[i]        = v;                   // row default = col
        out[OUTM + i] = v;                   // col (correct)
    }
}

// ---------------------------------------------------------------------------
// zero one chunk buffer (float4 grid-stride)
// ---------------------------------------------------------------------------
__global__ void zero_kernel(int bi)
{
    float4* p = (float4*)BUF(bi);
    size_t i  = (size_t)blockIdx.x * blockDim.x + threadIdx.x;
    size_t n4 = CTOT / 4;
    size_t st = (size_t)gridDim.x * blockDim.x;
    float4 z = make_float4(0.f, 0.f, 0.f, 0.f);
    for (; i < n4; i += st) p[i] = z;
}

// ---------------------------------------------------------------------------
// scatter edges of graphs [c0, c0+CH): A[(g-c0)*N + src_local][dst_local] = 1
// ---------------------------------------------------------------------------
__global__ void edge_kernel(const int* __restrict__ ei, int bi, int c0)
{
    float* A = BUF(bi);
    int e = blockIdx.x * blockDim.x + threadIdx.x;
    if (e >= NE) return;
    int src = ei[e];
    if (src < 0 || src >= G * NN) return;              // safety guard
    int g = src >> 10;
    if (g < c0 || g >= c0 + CH) return;
    int dst = ei[NE + e];
    A[((size_t)(src - (c0 << 10)) << 10) + (dst & 1023)] = 1.0f;
}

// add identity (self edge may already be 1.0 -> 2.0, matching adj + eye)
__global__ void diag_kernel(int bi)
{
    float* A = BUF(bi);
    int idx = blockIdx.x * blockDim.x + threadIdx.x;   // (g-c0)*1024 + i
    if (idx >= CH * NN) return;
    A[((size_t)idx << 10) + (idx & 1023)] += 1.0f;
}

// ---------------------------------------------------------------------------
// per-row degree (row sum, exact small integers) -> dis = 1/sqrt(deg)
// ---------------------------------------------------------------------------
__global__ void deg_kernel(int bi)
{
    __shared__ float sm[8];
    const float* r = BUF(bi) + ((size_t)blockIdx.x << 10);
    float s = 0.f;
    for (int j = threadIdx.x; j < NN; j += 256) s += r[j];
    #pragma unroll
    for (int o = 16; o; o >>= 1) s += __shfl_down_sync(0xffffffffu, s, o);
    if ((threadIdx.x & 31) == 0) sm[threadIdx.x >> 5] = s;
    __syncthreads();
    if (threadIdx.x == 0) {
        float tot = 0.f;
        #pragma unroll
        for (int w = 0; w < 8; w++) tot += sm[w];
        g_dis[blockIdx.x] = 1.0f / sqrtf(tot);
    }
}

// ---------------------------------------------------------------------------
// B = 0.95 * (dis_i * A * dis_j)   (in place over A),  S = I + B
// ---------------------------------------------------------------------------
__global__ void build_bs_kernel(int ba, int bs)
{
    float* A = BUF(ba);
    float* S = BUF(bs);
    size_t idx = (size_t)blockIdx.x * 256 + threadIdx.x;
    if (idx >= CTOT) return;
    int    j     = (int)(idx & 1023);
    size_t rowid = idx >> 10;                          // local g*1024 + i
    int    i     = (int)(rowid & 1023);
    int    gb    = (int)((rowid >> 10) << 10);
    float t = g_dis[rowid] * A[idx];
    t = t * g_dis[gb + j];
    float b = 0.95f * t;
    A[idx] = b;
    S[idx] = (i == j) ? (b + 1.0f) : b;
}

// ---------------------------------------------------------------------------
// batched SGEMM: D[g] = A[g] * B[g] (+ C[g] if bc >= 0)     1024^3, CH mats
// 128x128 block tile, BK=16, 256 threads, 8x8 per thread
// ---------------------------------------------------------------------------
__global__ __launch_bounds__(256, 2)
void gemm_kernel(int ba, int bb, int bc, int bd)
{
    __shared__ float As[16][132];
    __shared__ float Bs[16][132];

    const int g = blockIdx.z;
    const float* A = BUF(ba) + (size_t)g * MATS;
    const float* B = BUF(bb) + (size_t)g * MATS;
    float*       D = BUF(bd) + (size_t)g * MATS;
    const float* C = (bc >= 0) ? (BUF(bc) + (size_t)g * MATS) : (const float*)0;

    const int tid = threadIdx.x;
    const int tx  = tid & 15;
    const int ty  = tid >> 4;
    const int m0  = blockIdx.y * 128;
    const int n0  = blockIdx.x * 128;

    float acc[8][8];
    #pragma unroll
    for (int i = 0; i < 8; i++)
        #pragma unroll
        for (int j = 0; j < 8; j++) acc[i][j] = 0.0f;

    for (int kt = 0; kt < NN; kt += 16) {
        #pragma unroll
        for (int l = 0; l < 2; l++) {                  // A tile 128x16 -> As[k][m]
            int f = tid + l * 256;
            int r = f >> 2;
            int c = (f & 3) << 2;
            float4 v = *(const float4*)(A + (size_t)(m0 + r) * NN + kt + c);
            As[c + 0][r] = v.x; As[c + 1][r] = v.y;
            As[c + 2][r] = v.z; As[c + 3][r] = v.w;
        }
        #pragma unroll
        for (int l = 0; l < 2; l++) {                  // B tile 16x128
            int f = tid + l * 256;
            int r = f >> 5;
            int c = (f & 31) << 2;
            *(float4*)(&Bs[r][c]) = *(const float4*)(B + (size_t)(kt + r) * NN + n0 + c);
        }
        __syncthreads();
        #pragma unroll
        for (int k = 0; k < 16; k++) {
            float ra[8], rb[8];
            *(float4*)(ra)     = *(const float4*)(&As[k][ty * 8]);
            *(float4*)(ra + 4) = *(const float4*)(&As[k][ty * 8 + 4]);
            *(float4*)(rb)     = *(const float4*)(&Bs[k][tx * 8]);
            *(float4*)(rb + 4) = *(const float4*)(&Bs[k][tx * 8 + 4]);
            #pragma unroll
            for (int i = 0; i < 8; i++)
                #pragma unroll
                for (int j = 0; j < 8; j++)
                    acc[i][j] = fmaf(ra[i], rb[j], acc[i][j]);
        }
        __syncthreads();
    }

    #pragma unroll
    for (int i = 0; i < 8; i++) {
        size_t off = (size_t)(m0 + ty * 8 + i) * NN + n0 + tx * 8;
        if (C) {
            #pragma unroll
            for (int j = 0; j < 8; j++) acc[i][j] += C[off + j];
        }
        *(float4*)(D + off)     = *(float4*)(&acc[i][0]);
        *(float4*)(D + off + 4) = *(float4*)(&acc[i][4]);
    }
}

// ---------------------------------------------------------------------------
// per-graph transpose (so the column top-k reads are coalesced)
// ---------------------------------------------------------------------------
__global__ void transpose_kernel(int bs, int bt)
{
    __shared__ float tile[32][33];
    int g  = blockIdx.z;
    int i0 = blockIdx.y * 32;
    int j0 = blockIdx.x * 32;
    const float* Sg = BUF(bs) + ((size_t)g << 20);
    float*       Tg = BUF(bt) + ((size_t)g << 20);
    int x = threadIdx.x, y = threadIdx.y;              // 32 x 8
    #pragma unroll
    for (int r = 0; r < 32; r += 8)
        tile[y + r][x] = Sg[(size_t)(i0 + y + r) * NN + j0 + x];
    __syncthreads();
    #pragma unroll
    for (int r = 0; r < 32; r += 8)
        Tg[(size_t)(j0 + y + r) * NN + i0 + x] = tile[x][y + r];
}

// ---------------------------------------------------------------------------
// per-column top-128: full bitonic sort of 1024 keys
// key = (float_bits(v) << 32) | (1023 - row)  -> descending sort gives
// value-desc with smaller-index-first tie break (matches lax.top_k).
// all S entries are >= 0 so raw float bits order correctly.
// OUTPUT IS WRITTEN AS FLOAT32 (harness __output__ dtype).
// ---------------------------------------------------------------------------
__global__ __launch_bounds__(512)
void topk_kernel(int bt, float* __restrict__ out, int c0)
{
    __shared__ unsigned long long key[1024];
    const int col = blockIdx.x;                        // local: gl*1024 + j
    const int gg  = c0 + (col >> 10);                  // global graph id
    const float* row = BUF(bt) + ((size_t)col << 10);
    const int t = threadIdx.x;

    for (int i = t; i < 1024; i += 512) {
        unsigned vb = __float_as_uint(row[i]);
        key[i] = ((unsigned long long)vb << 32) | (unsigned)(1023 - i);
    }
    __syncthreads();

    for (int k = 2; k <= 1024; k <<= 1) {
        for (int j = k >> 1; j > 0; j >>= 1) {
            unsigned idx = ((t & ~(j - 1)) << 1) | (t & (j - 1));
            unsigned pi  = idx | j;
            bool desc = ((idx & k) == 0);
            unsigned long long a = key[idx], b = key[pi];
            if ((a < b) == desc) { key[idx] = b; key[pi] = a; }
            __syncthreads();
        }
    }

    if (t < KTOP) {
        unsigned long long kk = key[t];
        int i = 1023 - (int)(kk & 0xFFFFFFFFu);
        size_t base = ((size_t)(c0 << 10) + col) * KTOP + t;   // global col * K + t
        out[base]        = (float)((gg << 10) + i);            // row index + offset
        out[OUTM + base] = (float)((gg << 10) + (col & 1023)); // col index + offset
    }
}

// ---------------------------------------------------------------------------
extern "C" void kernel_launch(void* const* d_in, const int* in_sizes, int n_in,
                              void* d_out, int out_size)
{
    (void)out_size;
    // Select edge_index by element count (2 * NE = 4,194,304), robust to
    // metadata ordering. x has 8,388,608 elements, batch has 65,536.
    const int* ei = (const int*)d_in[n_in > 1 ? 1 : 0];
    for (int i = 0; i < n_in; i++) {
        if (in_sizes[i] == 2 * NE) { ei = (const int*)d_in[i]; break; }
    }
    float* out = (float*)d_out;

    // default-fill output first (valid cols everywhere; rows get overwritten)
    out_init_kernel<<<4096, 256>>>(out);

    dim3 gg(8, 8, CH);

    for (int c0 = 0; c0 < G; c0 += CH) {
        zero_kernel    <<<8192, 256>>>(0);
        edge_kernel    <<<NE / 256, 256>>>(ei, 0, c0);
        diag_kernel    <<<CH * NN / 256, 256>>>(0);
        deg_kernel     <<<CH * NN, 256>>>(0);
        build_bs_kernel<<<(unsigned)(CTOT / 256), 256>>>(0, 1);

        // b0 = B, b1 = S(=I+B), b2 free.  P2 = B*B -> b2
        gemm_kernel<<<gg, 256>>>(0, 0, -1, 2);

        // 3-buffer Neumann-doubling rotation: after 8 doublings S covers 512 terms
        int s = 1, p = 2, f = 0;
        for (int it = 0; it < 8; it++) {
            gemm_kernel<<<gg, 256>>>(p, s, s, f);       // S' = P*S + S -> f
            if (it < 7) {
                gemm_kernel<<<gg, 256>>>(p, p, -1, s);  // P' = P*P -> old s
                int ns = f, np = s, nf = p;
                s = ns; p = np; f = nf;
            } else {
                s = f;                                   // last: only S updated
            }
        }

        // transpose final S into a free buffer, then column-wise top-128
        int t = (s + 1) % 3;
        transpose_kernel<<<dim3(32, 32, CH), dim3(32, 8)>>>(s, t);
        topk_kernel<<<CH * NN, 512>>>(t, out, c0);
    }
}

// round 8
// speedup vs baseline: 1.1795x; 1.1795x over previous
#include <cuda_runtime.h>
#include <math.h>
#include <stdint.h>

#define G    64
#define NN   1024
#define KTOP 128
#define CH   16                              // graphs per chunk
#define NE   (G * NN * 32)                   // 2,097,152 edges
#define MATS ((size_t)NN * NN)               // 1,048,576
#define CTOT ((size_t)CH * MATS)             // 16,777,216 floats per buffer
#define OUTM ((size_t)G * NN * KTOP)         // 8,388,608

// 3 x 64MB rotating scratch buffers
__device__ __align__(16) float g_scratch[3 * CTOT];
__device__ __align__(16) float g_dis[CH * NN];

__device__ __forceinline__ float* BUF(int i) { return g_scratch + (size_t)i * CTOT; }

// ---------------------------------------------------------------------------
// initialize full output (float32 dtype): col half correct, row default = col
// ---------------------------------------------------------------------------
__global__ void out_init_kernel(float* __restrict__ out)
{
    size_t i  = (size_t)blockIdx.x * blockDim.x + threadIdx.x;
    size_t st = (size_t)gridDim.x * blockDim.x;
    for (; i < OUTM; i += st) {
        int g = (int)(i / (NN * KTOP));
        int j = (int)((i / KTOP) & 1023);
        float v = (float)((g << 10) + j);
        out[i]        = v;
        out[OUTM + i] = v;
    }
}

// ---------------------------------------------------------------------------
__global__ void zero_kernel(int bi)
{
    float4* p = (float4*)BUF(bi);
    size_t i  = (size_t)blockIdx.x * blockDim.x + threadIdx.x;
    size_t n4 = CTOT / 4;
    size_t st = (size_t)gridDim.x * blockDim.x;
    float4 z = make_float4(0.f, 0.f, 0.f, 0.f);
    for (; i < n4; i += st) p[i] = z;
}

// ---------------------------------------------------------------------------
__global__ void edge_kernel(const int* __restrict__ ei, int bi, int c0)
{
    float* A = BUF(bi);
    int e = blockIdx.x * blockDim.x + threadIdx.x;
    if (e >= NE) return;
    int src = ei[e];
    if (src < 0 || src >= G * NN) return;
    int g = src >> 10;
    if (g < c0 || g >= c0 + CH) return;
    int dst = ei[NE + e];
    A[((size_t)(src - (c0 << 10)) << 10) + (dst & 1023)] = 1.0f;
}

__global__ void diag_kernel(int bi)
{
    float* A = BUF(bi);
    int idx = blockIdx.x * blockDim.x + threadIdx.x;
    if (idx >= CH * NN) return;
    A[((size_t)idx << 10) + (idx & 1023)] += 1.0f;
}

// ---------------------------------------------------------------------------
__global__ void deg_kernel(int bi)
{
    __shared__ float sm[8];
    const float* r = BUF(bi) + ((size_t)blockIdx.x << 10);
    float s = 0.f;
    for (int j = threadIdx.x; j < NN; j += 256) s += r[j];
    #pragma unroll
    for (int o = 16; o; o >>= 1) s += __shfl_down_sync(0xffffffffu, s, o);
    if ((threadIdx.x & 31) == 0) sm[threadIdx.x >> 5] = s;
    __syncthreads();
    if (threadIdx.x == 0) {
        float tot = 0.f;
        #pragma unroll
        for (int w = 0; w < 8; w++) tot += sm[w];
        g_dis[blockIdx.x] = 1.0f / sqrtf(tot);
    }
}

// ---------------------------------------------------------------------------
__global__ void build_bs_kernel(int ba, int bs)
{
    float* A = BUF(ba);
    float* S = BUF(bs);
    size_t idx = (size_t)blockIdx.x * 256 + threadIdx.x;
    if (idx >= CTOT) return;
    int    j     = (int)(idx & 1023);
    size_t rowid = idx >> 10;
    int    i     = (int)(rowid & 1023);
    int    gb    = (int)((rowid >> 10) << 10);
    float t = g_dis[rowid] * A[idx];
    t = t * g_dis[gb + j];
    float b = 0.95f * t;
    A[idx] = b;
    S[idx] = (i == j) ? (b + 1.0f) : b;
}

// ---------------------------------------------------------------------------
// batched SGEMM, double-buffered: D[g] = A[g]*B[g] (+ C[g] if bc >= 0)
// 128x128 tile, BK=16, 256 threads, 8x8/thread, 2-stage smem pipeline
// ---------------------------------------------------------------------------
__global__ __launch_bounds__(256, 2)
void gemm_kernel(int ba, int bb, int bc, int bd)
{
    __shared__ float As[2][16][132];
    __shared__ float Bs[2][16][132];

    const int g = blockIdx.z;
    const float* A = BUF(ba) + (size_t)g * MATS;
    const float* B = BUF(bb) + (size_t)g * MATS;
    float*       D = BUF(bd) + (size_t)g * MATS;
    const float* C = (bc >= 0) ? (BUF(bc) + (size_t)g * MATS) : (const float*)0;

    const int tid = threadIdx.x;
    const int tx  = tid & 15;
    const int ty  = tid >> 4;
    const int m0  = blockIdx.y * 128;
    const int n0  = blockIdx.x * 128;

    // per-thread tile-load coordinates (2 float4 each for A and B)
    const int ar0 = tid >> 2,          ar1 = (tid + 256) >> 2;   // A rows 0..127
    const int ac  = (tid & 3) << 2;                              // A col 0/4/8/12
    const int br0 = tid >> 5,          br1 = (tid + 256) >> 5;   // B rows 0..15
    const int bcc = (tid & 31) << 2;                             // B col 0..124

    float4 pa0, pa1, pb0, pb1;

    // prologue: load tile 0 and store to stage 0
    pa0 = *(const float4*)(A + (size_t)(m0 + ar0) * NN + ac);
    pa1 = *(const float4*)(A + (size_t)(m0 + ar1) * NN + ac);
    pb0 = *(const float4*)(B + (size_t)br0 * NN + n0 + bcc);
    pb1 = *(const float4*)(B + (size_t)br1 * NN + n0 + bcc);
    As[0][ac + 0][ar0] = pa0.x; As[0][ac + 1][ar0] = pa0.y;
    As[0][ac + 2][ar0] = pa0.z; As[0][ac + 3][ar0] = pa0.w;
    As[0][ac + 0][ar1] = pa1.x; As[0][ac + 1][ar1] = pa1.y;
    As[0][ac + 2][ar1] = pa1.z; As[0][ac + 3][ar1] = pa1.w;
    *(float4*)(&Bs[0][br0][bcc]) = pb0;
    *(float4*)(&Bs[0][br1][bcc]) = pb1;
    __syncthreads();

    float acc[8][8];
    #pragma unroll
    for (int i = 0; i < 8; i++)
        #pragma unroll
        for (int j = 0; j < 8; j++) acc[i][j] = 0.0f;

    for (int kt = 0; kt < 64; kt++) {
        const int cur = kt & 1;
        if (kt < 63) {                          // prefetch next tile into regs
            int kb = (kt + 1) << 4;
            pa0 = *(const float4*)(A + (size_t)(m0 + ar0) * NN + kb + ac);
            pa1 = *(const float4*)(A + (size_t)(m0 + ar1) * NN + kb + ac);
            pb0 = *(const float4*)(B + (size_t)(kb + br0) * NN + n0 + bcc);
            pb1 = *(const float4*)(B + (size_t)(kb + br1) * NN + n0 + bcc);
        }
        #pragma unroll
        for (int k = 0; k < 16; k++) {
            float ra[8], rb[8];
            *(float4*)(ra)     = *(const float4*)(&As[cur][k][ty * 8]);
            *(float4*)(ra + 4) = *(const float4*)(&As[cur][k][ty * 8 + 4]);
            *(float4*)(rb)     = *(const float4*)(&Bs[cur][k][tx * 8]);
            *(float4*)(rb + 4) = *(const float4*)(&Bs[cur][k][tx * 8 + 4]);
            #pragma unroll
            for (int i = 0; i < 8; i++)
                #pragma unroll
                for (int j = 0; j < 8; j++)
                    acc[i][j] = fmaf(ra[i], rb[j], acc[i][j]);
        }
        if (kt < 63) {                          // store prefetched tile to other stage
            const int nst = cur ^ 1;
            As[nst][ac + 0][ar0] = pa0.x; As[nst][ac + 1][ar0] = pa0.y;
            As[nst][ac + 2][ar0] = pa0.z; As[nst][ac + 3][ar0] = pa0.w;
            As[nst][ac + 0][ar1] = pa1.x; As[nst][ac + 1][ar1] = pa1.y;
            As[nst][ac + 2][ar1] = pa1.z; As[nst][ac + 3][ar1] = pa1.w;
            *(float4*)(&Bs[nst][br0][bcc]) = pb0;
            *(float4*)(&Bs[nst][br1][bcc]) = pb1;
            __syncthreads();
        }
    }

    #pragma unroll
    for (int i = 0; i < 8; i++) {
        size_t off = (size_t)(m0 + ty * 8 + i) * NN + n0 + tx * 8;
        if (C) {
            #pragma unroll
            for (int j = 0; j < 8; j++) acc[i][j] += C[off + j];
        }
        *(float4*)(D + off)     = *(float4*)(&acc[i][0]);
        *(float4*)(D + off + 4) = *(float4*)(&acc[i][4]);
    }
}

// ---------------------------------------------------------------------------
__global__ void transpose_kernel(int bs, int bt)
{
    __shared__ float tile[32][33];
    int g  = blockIdx.z;
    int i0 = blockIdx.y * 32;
    int j0 = blockIdx.x * 32;
    const float* Sg = BUF(bs) + ((size_t)g << 20);
    float*       Tg = BUF(bt) + ((size_t)g << 20);
    int x = threadIdx.x, y = threadIdx.y;
    #pragma unroll
    for (int r = 0; r < 32; r += 8)
        tile[y + r][x] = Sg[(size_t)(i0 + y + r) * NN + j0 + x];
    __syncthreads();
    #pragma unroll
    for (int r = 0; r < 32; r += 8)
        Tg[(size_t)(j0 + y + r) * NN + i0 + x] = tile[x][y + r];
}

// ---------------------------------------------------------------------------
// per-column top-128 via bitonic sort of packed (valuebits<<32 | ~idx) keys
// ---------------------------------------------------------------------------
__global__ __launch_bounds__(512)
void topk_kernel(int bt, float* __restrict__ out, int c0)
{
    __shared__ unsigned long long key[1024];
    const int col = blockIdx.x;
    const int gg  = c0 + (col >> 10);
    const float* row = BUF(bt) + ((size_t)col << 10);
    const int t = threadIdx.x;

    for (int i = t; i < 1024; i += 512) {
        unsigned vb = __float_as_uint(row[i]);
        key[i] = ((unsigned long long)vb << 32) | (unsigned)(1023 - i);
    }
    __syncthreads();

    for (int k = 2; k <= 1024; k <<= 1) {
        for (int j = k >> 1; j > 0; j >>= 1) {
            unsigned idx = ((t & ~(j - 1)) << 1) | (t & (j - 1));
            unsigned pi  = idx | j;
            bool desc = ((idx & k) == 0);
            unsigned long long a = key[idx], b = key[pi];
            if ((a < b) == desc) { key[idx] = b; key[pi] = a; }
            __syncthreads();
        }
    }

    if (t < KTOP) {
        unsigned long long kk = key[t];
        int i = 1023 - (int)(kk & 0xFFFFFFFFu);
        size_t base = ((size_t)(c0 << 10) + col) * KTOP + t;
        out[base]        = (float)((gg << 10) + i);
        out[OUTM + base] = (float)((gg << 10) + (col & 1023));
    }
}

// ---------------------------------------------------------------------------
extern "C" void kernel_launch(void* const* d_in, const int* in_sizes, int n_in,
                              void* d_out, int out_size)
{
    (void)out_size;
    const int* ei = (const int*)d_in[n_in > 1 ? 1 : 0];
    for (int i = 0; i < n_in; i++) {
        if (in_sizes[i] == 2 * NE) { ei = (const int*)d_in[i]; break; }
    }
    float* out = (float*)d_out;

    out_init_kernel<<<4096, 256>>>(out);

    dim3 gg(8, 8, CH);

    for (int c0 = 0; c0 < G; c0 += CH) {
        zero_kernel    <<<8192, 256>>>(0);
        edge_kernel    <<<NE / 256, 256>>>(ei, 0, c0);
        diag_kernel    <<<CH * NN / 256, 256>>>(0);
        deg_kernel     <<<CH * NN, 256>>>(0);
        build_bs_kernel<<<(unsigned)(CTOT / 256), 256>>>(0, 1);

        // b0 = B, b1 = S(=I+B), b2 free.  P2 = B*B -> b2
        gemm_kernel<<<gg, 256>>>(0, 0, -1, 2);

        // 3-buffer Neumann-doubling rotation: 8 doublings -> S covers 512 terms
        int s = 1, p = 2, f = 0;
        for (int it = 0; it < 8; it++) {
            gemm_kernel<<<gg, 256>>>(p, s, s, f);       // S' = P*S + S -> f
            if (it < 7) {
                gemm_kernel<<<gg, 256>>>(p, p, -1, s);  // P' = P*P -> old s
                int ns = f, np = s, nf = p;
                s = ns; p = np; f = nf;
            } else {
                s = f;
            }
        }

        int t = (s + 1) % 3;
        transpose_kernel<<<dim3(32, 32, CH), dim3(32, 8)>>>(s, t);
        topk_kernel<<<CH * NN, 512>>>(t, out, c0);
    }
}